// round 10
// baseline (speedup 1.0000x reference)
#include <cuda_runtime.h>
#include <math.h>

#define NQ0 1000
#define NQ1 500
#define MP  512          // padded+bordered Schur dim: 500 S + 11 identity + 1 border(u)
#define G0P 1024
#define NB  64
#define NPAN (MP/NB)     // 8
#define CL  8            // cluster size
#define NT  512          // threads per CTA (16 warps) — empirically optimal
#define GT  (CL*NT)      // 4096 cluster-wide threads
#define NMAX 8192
#define UROW (MP-1)      // 511: border row holding u

// ---------------- device scratch ----------------
static __device__ float g_S[MP*MP];
static __device__ float g_n0[G0P], g_s0[G0P], g_w0[G0P], g_ws0[G0P];
static __device__ float g_n1[MP],  g_s1[MP];
static __device__ int   g_off[G0P+1];
static __device__ int   g_cur[G0P];
static __device__ unsigned short g_csr[NMAX];
static __device__ int   g_i0[NMAX], g_i1[NMAX];
static __device__ double g_rTr, g_ldD0, g_q0;

#define CLUSTER_SYNC() do { \
    asm volatile("barrier.cluster.arrive.aligned;" ::: "memory"); \
    asm volatile("barrier.cluster.wait.aligned;"   ::: "memory"); } while (0)

// =================== single fused cluster kernel ===========================
__global__ void __cluster_dims__(CL,1,1) __launch_bounds__(NT,1)
k_all(const float* __restrict__ yt, const float* __restrict__ yp,
      const void* z0, const void* z1,
      const float* __restrict__ sig2e, const float* __restrict__ sig2bs,
      float* __restrict__ out, int n)
{
    __shared__ float Ld[NB][NB+1];      // diag block of trapezoid / SYRK Li tile
    __shared__ float Bs[NB][NB+1];      // TRSM block of trapezoid / SYRK Lj tile
    __shared__ float colbuf[2*NB][17];  // eliminated odd columns (half-width, 2 passes)
    __shared__ float dinv[NB];
    __shared__ float s_quad;
    __shared__ double sred[3][16];
    __shared__ int   wsum[16];
    __shared__ int   s_is64;

    int rank = blockIdx.x;
    int tid  = threadIdx.x;
    int lane = tid & 31, wid = tid >> 5;
    int gt   = rank * NT + tid;

    // ---------------- A: zero scratch + detect index width -----------------
    {
        float4* S4 = (float4*)g_S;
        const float4 z4 = make_float4(0.f,0.f,0.f,0.f);
        for (int i = gt; i < (MP*MP)/4; i += GT) S4[i] = z4;
        if (gt < G0P) { g_n0[gt]=0.f; g_s0[gt]=0.f; g_cur[gt]=0; }
        if (gt < MP)  { g_n1[gt]=0.f; g_s1[gt]=0.f; }
        if (gt == 0)  { g_rTr=0.0; g_ldD0=0.0; g_q0=0.0; g_off[0]=0; }
        if (wid == 0) {
            const unsigned int* w = (const unsigned int*)z0;
            unsigned int v = w[1+2*lane] | w[65+2*lane];
            unsigned int nz = __ballot_sync(0xffffffffu, v != 0u);
            if (lane == 0) s_is64 = (nz == 0u);
        }
    }
    __threadfence(); CLUSTER_SYNC();
    int is64 = s_is64;

    // ---------------- B: scatter (counts, sums, rTr) -----------------------
    double rtr = 0.0;
    for (int i = gt; i < n && i < NMAX; i += GT) {
        float r = yt[i] - yp[i];
        int a, b;
        if (is64) { a=(int)((const long long*)z0)[i]; b=(int)((const long long*)z1)[i]; }
        else      { a=((const int*)z0)[i];            b=((const int*)z1)[i]; }
        if ((unsigned)a < (unsigned)NQ0 && (unsigned)b < (unsigned)NQ1) {
            g_i0[i]=a; g_i1[i]=b;
            atomicAdd(&g_n0[a],1.f); atomicAdd(&g_s0[a],r);
            atomicAdd(&g_n1[b],1.f); atomicAdd(&g_s1[b],r);
            rtr += (double)r * (double)r;
        } else { g_i0[i]=0; g_i1[i]=0; }
    }
    #pragma unroll
    for (int o=16;o;o>>=1) rtr += __shfl_down_sync(0xffffffffu, rtr, o);
    if (lane==0) sred[0][wid] = rtr;
    __syncthreads();
    if (tid==0){ double s=0; for (int k2=0;k2<16;k2++) s+=sred[0][k2]; atomicAdd(&g_rTr,s); }
    __threadfence(); CLUSTER_SYNC();

    // ---------------- C: prep + prefix scan (rank 0) -----------------------
    float e = sig2e[0], b0 = sig2bs[0], b1 = sig2bs[1];
    float sqb1 = sqrtf(b1);
    {
        double ld = 0.0, q = 0.0;
        for (int i = gt; i < G0P + MP; i += GT) {
            if (i < G0P) {
                float cnt = __ldcg(&g_n0[i]);
                float s0v = __ldcg(&g_s0[i]);
                float d0 = e + b0*cnt, w = 1.f/d0;
                g_w0[i] = w; g_ws0[i] = s0v*w;
                if (i < NQ0) {
                    ld += log((double)d0);
                    q  += (double)b0*(double)s0v*(double)s0v*(double)w;
                }
            } else {
                int j = i - G0P;
                if (j < NQ1) {
                    g_S[j*MP+j] = e + b1*__ldcg(&g_n1[j]);
                    g_S[UROW*MP+j] = sqb1*__ldcg(&g_s1[j]);   // border row = u
                } else if (j < UROW) g_S[j*MP+j] = 1.f;       // identity padding
            }
        }
        #pragma unroll
        for (int o=16;o;o>>=1) {
            ld += __shfl_down_sync(0xffffffffu, ld, o);
            q  += __shfl_down_sync(0xffffffffu, q,  o);
        }
        if (lane==0) { sred[1][wid]=ld; sred[2][wid]=q; }
        __syncthreads();
        if (tid==0) {
            double a1=0,a2=0;
            for (int k2=0;k2<16;k2++){a1+=sred[1][k2];a2+=sred[2][k2];}
            atomicAdd(&g_ldD0,a1); atomicAdd(&g_q0,a2);
        }
    }
    if (rank == 0) {   // scan: 512 threads x 2 elements
        int base = tid*2;
        int c0i=(int)__ldcg(&g_n0[base]), c1i=(int)__ldcg(&g_n0[base+1]);
        int s = c0i+c1i;
        int v = s;
        #pragma unroll
        for (int o=1;o<32;o<<=1){int y=__shfl_up_sync(0xffffffffu,v,o); if(lane>=o)v+=y;}
        if (lane==31) wsum[wid]=v;
        __syncthreads();
        if (wid==0 && lane<16){
            int wv=wsum[lane];
            #pragma unroll
            for (int o=1;o<16;o<<=1){int y=__shfl_up_sync(0xffffu,wv,o); if(lane>=o)wv+=y;}
            wsum[lane]=wv;
        }
        __syncthreads();
        int excl = v - s + (wid ? wsum[wid-1] : 0);
        g_off[base+1]=excl+c0i;
        g_off[base+2]=excl+s;
    }
    __threadfence(); CLUSTER_SYNC();

    // ---------------- D: csr build + u correction --------------------------
    {
        float ucoef = -sqb1 * b0;
        for (int i = gt; i < n && i < NMAX; i += GT) {
            int a = g_i0[i], b = g_i1[i];
            int ppos = atomicAdd(&g_cur[a], 1);
            g_csr[__ldcg(&g_off[a]) + ppos] = (unsigned short)b;
            atomicAdd(&g_S[UROW*MP + b], ucoef * __ldcg(&g_ws0[a]));
        }
    }
    __threadfence(); CLUSTER_SYNC();

    // ---------------- E: pairs (sparse C^T D0^{-1} C, no integer div) ------
    {
        int gw = rank*16 + wid;
        for (int g = gw; g < NQ0; g += CL*16) {
            int lo  = __ldcg(&g_off[g]);
            int len = __ldcg(&g_off[g+1]) - lo;
            if (!len) continue;
            float coef = -b0*b1*__ldcg(&g_w0[g]);
            for (int ia = 0; ia < len; ia++) {
                int a = (int)__ldcg(&g_csr[lo + ia]);
                float* rowp = &g_S[a*MP];
                for (int ib = lane; ib < len; ib += 32) {
                    int b = (int)__ldcg(&g_csr[lo + ib]);
                    atomicAdd(&rowp[b], coef);
                }
            }
        }
    }
    __threadfence(); CLUSTER_SYNC();

    // ---------------- F: bordered Cholesky, fused trapezoid panels ---------
    // Each panel: CTA factors the diag block (redundantly) WITH its TRSM row
    // block riding the same rank-2 eliminations (trapezoid) -> TRSM for free.
    float logsum = 0.f;   // tid<64: per-diag-slot sum of log(pivot)
    int tx = lane, ty = wid;   // 16 row-streams x 32 col-lanes

    for (int p = 0; p < NPAN; p++) {
        int c0 = p*NB;
        int r = p + 1 + rank;
        int hasB = (r < NPAN);
        int r0 = r*NB;
        // load diag block (+ TRSM block if owned), float4, L1-bypass
        for (int t2 = tid; t2 < NB*16; t2 += NT) {
            int i = t2 >> 4, j4 = (t2 & 15) << 2;
            float4 v = __ldcg((const float4*)&g_S[(c0+i)*MP + c0 + j4]);
            Ld[i][j4]=v.x; Ld[i][j4+1]=v.y; Ld[i][j4+2]=v.z; Ld[i][j4+3]=v.w;
        }
        if (hasB) for (int t2 = tid; t2 < NB*16; t2 += NT) {
            int i = t2 >> 4, j4 = (t2 & 15) << 2;
            float4 v = __ldcg((const float4*)&g_S[(r0+i)*MP + c0 + j4]);
            Bs[i][j4]=v.x; Bs[i][j4+1]=v.y; Bs[i][j4+2]=v.z; Bs[i][j4+3]=v.w;
        }
        __syncthreads();

        // --- batched rank-2 deferred-scaling elimination over trapezoid ---
        #pragma unroll 1
        for (int half = 0; half < 2; half++) {
            #pragma unroll 1
            for (int bb = 0; bb < 16; bb++) {
                int b = half*16 + bb;
                int k = 2*b;
                float dk  = Ld[k][k];
                float ivk = __frcp_rn(dk);
                float tco = Ld[k+1][k]*ivk;
                float dk1 = Ld[k+1][k+1] - Ld[k+1][k]*tco;
                float ivk1= __frcp_rn(dk1);
                int j0 = k+2+tx, j1 = j0+32;
                float c0v=0.f, e0v=0.f, c1v=0.f, e1v=0.f;
                if (j0 < NB){ float a=Ld[j0][k]; float ap=Ld[j0][k+1]-a*tco; c0v=a*ivk; e0v=ap*ivk1; }
                if (j1 < NB){ float a=Ld[j1][k]; float ap=Ld[j1][k+1]-a*tco; c1v=a*ivk; e1v=ap*ivk1; }
                // diag rows (triangular)
                for (int i = k+1+ty; i < NB; i += 16) {
                    float aik = Ld[i][k], aik1 = Ld[i][k+1];
                    float api = aik1 - aik*tco;
                    if (tx == 0) colbuf[i][bb] = api;
                    if (j0 <= i) Ld[i][j0] -= aik*c0v + api*e0v;
                    if (j1 <= i) Ld[i][j1] -= aik*c1v + api*e1v;
                }
                // trapezoid rows (full rectangle)
                if (hasB) for (int i = ty; i < NB; i += 16) {
                    float bik = Bs[i][k], bik1 = Bs[i][k+1];
                    float bpi = bik1 - bik*tco;
                    if (tx == 0) colbuf[NB+i][bb] = bpi;
                    if (j0 < NB) Bs[i][j0] -= bik*c0v + bpi*e0v;
                    if (j1 < NB) Bs[i][j1] -= bik*c1v + bpi*e1v;
                }
                __syncthreads();
            }
            // restore this half's odd columns (post-elimination values)
            for (int t2 = tid; t2 < NB*16; t2 += NT) {
                int i = t2 >> 4, bb = t2 & 15;
                int j = 2*(half*16+bb)+1;
                if (i >= j) Ld[i][j] = colbuf[i][bb];
            }
            if (hasB) for (int t2 = tid; t2 < NB*16; t2 += NT) {
                int i = t2 >> 4, bb = t2 & 15;
                int j = 2*(half*16+bb)+1;
                Bs[i][j] = colbuf[NB+i][bb];
            }
            __syncthreads();
        }

        // scaling: pivots -> dinv/log; scale diag lower + full trapezoid ----
        if (tid < NB) {
            float v = Ld[tid][tid];
            if (p == NPAN-1 && tid == NB-1) { s_quad = v; dinv[tid] = 1.f; }
            else { dinv[tid] = rsqrtf(v); logsum += logf(v); }   // log d_k
        }
        __syncthreads();
        for (int t2 = tid; t2 < NB*NB; t2 += NT) {
            int i = t2 >> 6, j = t2 & 63;
            if (i > j) Ld[i][j] *= dinv[j];
        }
        if (hasB) for (int t2 = tid; t2 < NB*NB; t2 += NT) {
            int i = t2 >> 6, j = t2 & 63;
            Bs[i][j] *= dinv[j];
        }
        __syncthreads();

        // writeback TRSM result
        if (hasB) for (int t2 = tid; t2 < NB*16; t2 += NT) {
            int i = t2 >> 4, j4 = (t2 & 15) << 2;
            float4 v = make_float4(Bs[i][j4],Bs[i][j4+1],Bs[i][j4+2],Bs[i][j4+3]);
            *(float4*)&g_S[(r0+i)*MP + c0 + j4] = v;
        }

        if (p < NPAN-1) {
            __threadfence(); CLUSTER_SYNC();
            // --- SYRK trailing update, tiles distributed over cluster ------
            int T = NPAN-1-p;
            int ntiles = T*(T+1)/2;
            for (int t0 = rank; t0 < ntiles; t0 += CL) {
                int idx = t0, bi = 0;
                while (idx >= bi+1){ idx -= bi+1; bi++; }
                int bj = idx;
                int rI = (p+1+bi)*NB, rJ = (p+1+bj)*NB;
                for (int t2 = tid; t2 < NB*16; t2 += NT) {
                    int i = t2 >> 4, j4 = (t2 & 15) << 2;
                    float4 v = __ldcg((const float4*)&g_S[(rI+i)*MP + c0 + j4]);
                    Ld[i][j4]=v.x; Ld[i][j4+1]=v.y; Ld[i][j4+2]=v.z; Ld[i][j4+3]=v.w;
                }
                if (bi != bj) {
                    for (int t2 = tid; t2 < NB*16; t2 += NT) {
                        int i = t2 >> 4, j4 = (t2 & 15) << 2;
                        float4 v = __ldcg((const float4*)&g_S[(rJ+i)*MP + c0 + j4]);
                        Bs[i][j4]=v.x; Bs[i][j4+1]=v.y; Bs[i][j4+2]=v.z; Bs[i][j4+3]=v.w;
                    }
                }
                __syncthreads();
                float (*Lj)[NB+1] = (bi==bj) ? Ld : Bs;
                // 512 threads: 2 rows x 4 cols each
                int sx = tid & 15, sy = tid >> 4;
                float acc[2][4] = {};
                #pragma unroll 4
                for (int kk = 0; kk < NB; kk++) {
                    float av[2], bv[4];
                    av[0]=Ld[sy*2][kk]; av[1]=Ld[sy*2+1][kk];
                    #pragma unroll
                    for (int v2=0;v2<4;v2++) bv[v2]=Lj[sx*4+v2][kk];
                    #pragma unroll
                    for (int u=0;u<2;u++)
                        #pragma unroll
                        for (int v2=0;v2<4;v2++) acc[u][v2] += av[u]*bv[v2];
                }
                #pragma unroll
                for (int u=0;u<2;u++) {
                    float* ptr = &g_S[(rI+sy*2+u)*MP + rJ + sx*4];
                    float4 old = __ldcg((const float4*)ptr);
                    old.x -= acc[u][0]; old.y -= acc[u][1];
                    old.z -= acc[u][2]; old.w -= acc[u][3];
                    *(float4*)ptr = old;
                }
                __syncthreads();
            }
            __threadfence(); CLUSTER_SYNC();
        }
    }

    // ---------------- epilogue: loss (rank 0) ------------------------------
    if (rank == 0) {
        if (tid < NB) dinv[tid] = logsum;
        __syncthreads();
        if (tid == 0) {
            float l = 0.f;
            for (int k2 = 0; k2 < NB; k2++) l += dinv[k2];   // logdet S
            double quad1 = -(double)s_quad;
            double ed = (double)e;
            double rTrv = __ldcg(&g_rTr);
            double ldD0v = __ldcg(&g_ldD0);
            double q0v  = __ldcg(&g_q0);
            double logdetV = (double)(n - (NQ0 + NQ1)) * log(ed) + ldD0v + (double)l;
            double quad = (rTrv - q0v - quad1) / ed;
            double loss = 0.5 * (double)n * 1.8378770664093454836
                        + 0.5 * logdetV + 0.5 * quad;
            out[0] = (float)loss;
        }
    }
}

// ---------------- host launcher --------------------------------------------
extern "C" void kernel_launch(void* const* d_in, const int* in_sizes, int n_in,
                              void* d_out, int out_size) {
    const float* y_true = (const float*)d_in[0];
    const float* y_pred = (const float*)d_in[1];
    const void*  z0     = d_in[2];
    const void*  z1     = d_in[3];
    const float* sig2e  = (const float*)d_in[4];
    const float* sig2bs = (const float*)d_in[5];
    float* out = (float*)d_out;
    int n = in_sizes[0];

    k_all<<<CL, NT>>>(y_true, y_pred, z0, z1, sig2e, sig2bs, out, n);
}

// round 11
// speedup vs baseline: 1.3157x; 1.3157x over previous
#include <cuda_runtime.h>
#include <math.h>

#define NQ0 1000
#define NQ1 500
#define MP  512          // padded+bordered Schur dim: 500 S + 11 identity + 1 border(u)
#define G0P 1024
#define NB  64
#define NPAN (MP/NB)     // 8
#define CL  8            // cluster size
#define NT  512          // threads per CTA (16 warps) — empirically optimal
#define GT  (CL*NT)      // 4096 cluster-wide threads
#define NMAX 8192
#define UROW (MP-1)      // 511: border row holding u

// ---------------- device scratch ----------------
static __device__ float g_S[MP*MP];
static __device__ float g_n0[G0P], g_s0[G0P], g_w0[G0P], g_ws0[G0P];
static __device__ float g_n1[MP],  g_s1[MP];
static __device__ int   g_off[G0P+1];
static __device__ int   g_cur[G0P];
static __device__ unsigned short g_csr[NMAX];
static __device__ int   g_i0[NMAX], g_i1[NMAX];
static __device__ double g_rTr, g_ldD0, g_q0;

// barrier.cluster.arrive has RELEASE semantics (PTX default), wait has ACQUIRE:
// all cross-CTA traffic here is __ldcg / atomics (L2), so no __threadfence needed.
#define CLUSTER_SYNC() do { \
    asm volatile("barrier.cluster.arrive.aligned;" ::: "memory"); \
    asm volatile("barrier.cluster.wait.aligned;"   ::: "memory"); } while (0)

// =================== single fused cluster kernel ===========================
__global__ void __cluster_dims__(CL,1,1) __launch_bounds__(NT,1)
k_all(const float* __restrict__ yt, const float* __restrict__ yp,
      const void* z0, const void* z1,
      const float* __restrict__ sig2e, const float* __restrict__ sig2bs,
      float* __restrict__ out, int n)
{
    __shared__ float Ld[NB][NB+1];      // diag factor / SYRK Li tile
    __shared__ float Bs[NB][NB+1];      // TRSM tile / SYRK Lj tile
    __shared__ float colbuf[NB][49];    // eliminated cols (3 per rank-4 batch x16)
    __shared__ float dinv[NB];
    __shared__ float s_quad;
    __shared__ double sred[3][16];
    __shared__ int   wsum[16];
    __shared__ int   s_is64;

    int rank = blockIdx.x;
    int tid  = threadIdx.x;
    int lane = tid & 31, wid = tid >> 5;
    int gt   = rank * NT + tid;

    // ---------------- A: zero scratch + detect index width -----------------
    {
        float4* S4 = (float4*)g_S;
        const float4 z4 = make_float4(0.f,0.f,0.f,0.f);
        for (int i = gt; i < (MP*MP)/4; i += GT) S4[i] = z4;
        if (gt < G0P) { g_n0[gt]=0.f; g_s0[gt]=0.f; g_cur[gt]=0; }
        if (gt < MP)  { g_n1[gt]=0.f; g_s1[gt]=0.f; }
        if (gt == 0)  { g_rTr=0.0; g_ldD0=0.0; g_q0=0.0; g_off[0]=0; }
        if (wid == 0) {
            const unsigned int* w = (const unsigned int*)z0;
            unsigned int v = w[1+2*lane] | w[65+2*lane];
            unsigned int nz = __ballot_sync(0xffffffffu, v != 0u);
            if (lane == 0) s_is64 = (nz == 0u);
        }
    }
    CLUSTER_SYNC();
    int is64 = s_is64;

    // ---------------- B: scatter (counts, sums, rTr) -----------------------
    double rtr = 0.0;
    for (int i = gt; i < n && i < NMAX; i += GT) {
        float r = yt[i] - yp[i];
        int a, b;
        if (is64) { a=(int)((const long long*)z0)[i]; b=(int)((const long long*)z1)[i]; }
        else      { a=((const int*)z0)[i];            b=((const int*)z1)[i]; }
        if ((unsigned)a < (unsigned)NQ0 && (unsigned)b < (unsigned)NQ1) {
            g_i0[i]=a; g_i1[i]=b;
            atomicAdd(&g_n0[a],1.f); atomicAdd(&g_s0[a],r);
            atomicAdd(&g_n1[b],1.f); atomicAdd(&g_s1[b],r);
            rtr += (double)r * (double)r;
        } else { g_i0[i]=0; g_i1[i]=0; }
    }
    #pragma unroll
    for (int o=16;o;o>>=1) rtr += __shfl_down_sync(0xffffffffu, rtr, o);
    if (lane==0) sred[0][wid] = rtr;
    __syncthreads();
    if (tid==0){ double s=0; for (int k2=0;k2<16;k2++) s+=sred[0][k2]; atomicAdd(&g_rTr,s); }
    CLUSTER_SYNC();

    // ---------------- C: prep + prefix scan (rank 0) -----------------------
    float e = sig2e[0], b0 = sig2bs[0], b1 = sig2bs[1];
    float sqb1 = sqrtf(b1);
    {
        double ld = 0.0, q = 0.0;
        for (int i = gt; i < G0P + MP; i += GT) {
            if (i < G0P) {
                float cnt = __ldcg(&g_n0[i]);
                float s0v = __ldcg(&g_s0[i]);
                float d0 = e + b0*cnt, w = 1.f/d0;
                g_w0[i] = w; g_ws0[i] = s0v*w;
                if (i < NQ0) {
                    ld += log((double)d0);
                    q  += (double)b0*(double)s0v*(double)s0v*(double)w;
                }
            } else {
                int j = i - G0P;
                if (j < NQ1) {
                    g_S[j*MP+j] = e + b1*__ldcg(&g_n1[j]);
                    g_S[UROW*MP+j] = sqb1*__ldcg(&g_s1[j]);   // border row = u
                } else if (j < UROW) g_S[j*MP+j] = 1.f;       // identity padding
            }
        }
        #pragma unroll
        for (int o=16;o;o>>=1) {
            ld += __shfl_down_sync(0xffffffffu, ld, o);
            q  += __shfl_down_sync(0xffffffffu, q,  o);
        }
        if (lane==0) { sred[1][wid]=ld; sred[2][wid]=q; }
        __syncthreads();
        if (tid==0) {
            double a1=0,a2=0;
            for (int k2=0;k2<16;k2++){a1+=sred[1][k2];a2+=sred[2][k2];}
            atomicAdd(&g_ldD0,a1); atomicAdd(&g_q0,a2);
        }
    }
    if (rank == 0) {   // scan: 512 threads x 2 elements
        int base = tid*2;
        int c0i=(int)__ldcg(&g_n0[base]), c1i=(int)__ldcg(&g_n0[base+1]);
        int s = c0i+c1i;
        int v = s;
        #pragma unroll
        for (int o=1;o<32;o<<=1){int y=__shfl_up_sync(0xffffffffu,v,o); if(lane>=o)v+=y;}
        if (lane==31) wsum[wid]=v;
        __syncthreads();
        if (wid==0 && lane<16){
            int wv=wsum[lane];
            #pragma unroll
            for (int o=1;o<16;o<<=1){int y=__shfl_up_sync(0xffffu,wv,o); if(lane>=o)wv+=y;}
            wsum[lane]=wv;
        }
        __syncthreads();
        int excl = v - s + (wid ? wsum[wid-1] : 0);
        g_off[base+1]=excl+c0i;
        g_off[base+2]=excl+s;
    }
    CLUSTER_SYNC();

    // ---------------- D: csr build + u correction --------------------------
    {
        float ucoef = -sqb1 * b0;
        for (int i = gt; i < n && i < NMAX; i += GT) {
            int a = g_i0[i], b = g_i1[i];
            int ppos = atomicAdd(&g_cur[a], 1);
            g_csr[__ldcg(&g_off[a]) + ppos] = (unsigned short)b;
            atomicAdd(&g_S[UROW*MP + b], ucoef * __ldcg(&g_ws0[a]));
        }
    }
    CLUSTER_SYNC();

    // ---------------- E: pairs (sparse C^T D0^{-1} C, shfl broadcast) ------
    {
        int gw = rank*16 + wid;
        for (int g = gw; g < NQ0; g += CL*16) {
            int lo  = __ldcg(&g_off[g]);
            int len = __ldcg(&g_off[g+1]) - lo;
            if (!len) continue;
            float coef = -b0*b1*__ldcg(&g_w0[g]);
            if (len <= 32) {
                int bv = 0;
                if (lane < len) bv = (int)__ldcg(&g_csr[lo + lane]);
                for (int ia = 0; ia < len; ia++) {
                    int a = __shfl_sync(0xffffffffu, bv, ia);
                    if (lane < len) atomicAdd(&g_S[a*MP + bv], coef);
                }
            } else {
                for (int ia = 0; ia < len; ia++) {
                    int a = (int)__ldcg(&g_csr[lo + ia]);
                    float* rowp = &g_S[a*MP];
                    for (int ib = lane; ib < len; ib += 32) {
                        int b = (int)__ldcg(&g_csr[lo + ib]);
                        atomicAdd(&rowp[b], coef);
                    }
                }
            }
        }
    }
    CLUSTER_SYNC();

    // ---------------- F: bordered blocked Cholesky (rank-4 batches) --------
    float logsum = 0.f;   // tid<64: per-diag-slot sum of log(pivot)
    int tx = lane, ty = wid;   // 16 row-streams x 32 col-lanes

    for (int p = 0; p < NPAN; p++) {
        int c0 = p*NB;
        // load diag block (float4, L1-bypass)
        for (int t2 = tid; t2 < NB*16; t2 += NT) {
            int i = t2 >> 4, j4 = (t2 & 15) << 2;
            float4 v = __ldcg((const float4*)&g_S[(c0+i)*MP + c0 + j4]);
            Ld[i][j4]=v.x; Ld[i][j4+1]=v.y; Ld[i][j4+2]=v.z; Ld[i][j4+3]=v.w;
        }
        __syncthreads();

        // --- rank-4 deferred-scaling elimination: 16 batches, 1 barrier each
        #pragma unroll 1
        for (int bb = 0; bb < 16; bb++) {
            int k = bb*4;
            // 4x4 head (redundant in all threads): LDL^T of leading block
            float A00=Ld[k][k];
            float A10=Ld[k+1][k], A11=Ld[k+1][k+1];
            float A20=Ld[k+2][k], A21=Ld[k+2][k+1], A22=Ld[k+2][k+2];
            float A30=Ld[k+3][k], A31=Ld[k+3][k+1], A32=Ld[k+3][k+2], A33=Ld[k+3][k+3];
            float r0=__frcp_rn(A00);
            float t10=A10*r0;
            float d1=A11-A10*t10;  float r1=__frcp_rn(d1);
            float t20=A20*r0;
            float bp21=A21-A20*t10; float t21=bp21*r1;
            float d2=A22-A20*t20-bp21*t21; float r2=__frcp_rn(d2);
            float t30=A30*r0;
            float bp31=A31-A30*t10; float t31=bp31*r1;
            float bp32=A32-A30*t20-bp31*t21; float t32=bp32*r2;
            float d3=A33-A30*t30-bp31*t31-bp32*t32; float r3=__frcp_rn(d3);
            // per-thread column multipliers (j as lower-triangle row index)
            int j0=k+4+tx, j1=j0+32;
            float c00=0.f,c01=0.f,c02=0.f,c03=0.f;
            float c10=0.f,c11=0.f,c12=0.f,c13=0.f;
            if (j0 < NB) {
                float a0=Ld[j0][k],a1=Ld[j0][k+1],a2=Ld[j0][k+2],a3=Ld[j0][k+3];
                float b1v=a1-a0*t10;
                float b2v=a2-a0*t20-b1v*t21;
                float b3v=a3-a0*t30-b1v*t31-b2v*t32;
                c00=a0*r0; c01=b1v*r1; c02=b2v*r2; c03=b3v*r3;
            }
            if (j1 < NB) {
                float a0=Ld[j1][k],a1=Ld[j1][k+1],a2=Ld[j1][k+2],a3=Ld[j1][k+3];
                float b1v=a1-a0*t10;
                float b2v=a2-a0*t20-b1v*t21;
                float b3v=a3-a0*t30-b1v*t31-b2v*t32;
                c10=a0*r0; c11=b1v*r1; c12=b2v*r2; c13=b3v*r3;
            }
            for (int i = k+1+ty; i < NB; i += 16) {
                float a0=Ld[i][k],a1=Ld[i][k+1],a2=Ld[i][k+2],a3=Ld[i][k+3];
                float b1v=a1-a0*t10;
                float b2v=a2-a0*t20-b1v*t21;
                float b3v=a3-a0*t30-b1v*t31-b2v*t32;
                if (tx == 0) {
                    colbuf[i][bb*3]   = b1v;
                    colbuf[i][bb*3+1] = b2v;
                    colbuf[i][bb*3+2] = b3v;
                }
                if (j0 <= i) Ld[i][j0] -= a0*c00 + b1v*c01 + b2v*c02 + b3v*c03;
                if (j1 <= i) Ld[i][j1] -= a0*c10 + b1v*c11 + b2v*c12 + b3v*c13;
            }
            __syncthreads();
        }
        // restore eliminated columns (final unscaled values incl. diagonals)
        for (int t2 = tid; t2 < NB*16; t2 += NT) {
            int i = t2 >> 4, bb = t2 & 15;
            int jb = bb*4, c = bb*3;
            float v1 = colbuf[i][c], v2 = colbuf[i][c+1], v3 = colbuf[i][c+2];
            if (i >= jb+1) Ld[i][jb+1] = v1;
            if (i >= jb+2) Ld[i][jb+2] = v2;
            if (i >= jb+3) Ld[i][jb+3] = v3;
        }
        __syncthreads();
        // scaling: pivots -> dinv/log; scale strictly-lower columns
        if (tid < NB) {
            float v = Ld[tid][tid];
            if (p == NPAN-1 && tid == NB-1) { s_quad = v; dinv[tid] = 1.f; }
            else { dinv[tid] = rsqrtf(v); logsum += logf(v); }   // log d_k
        }
        __syncthreads();
        for (int t2 = tid; t2 < NB*NB; t2 += NT) {
            int i = t2 >> 6, j = t2 & 63;
            if (i > j) Ld[i][j] *= dinv[j];
        }
        __syncthreads();

        // --- blocked right-looking TRSM: CTA `rank` owns row panel p+1+rank
        int r = p + 1 + rank;
        if (r < NPAN) {
            int r0 = r*NB;
            for (int t2 = tid; t2 < NB*16; t2 += NT) {
                int i = t2 >> 4, j4 = (t2 & 15) << 2;
                float4 v = __ldcg((const float4*)&g_S[(r0+i)*MP + c0 + j4]);
                Bs[i][j4]=v.x; Bs[i][j4+1]=v.y; Bs[i][j4+2]=v.z; Bs[i][j4+3]=v.w;
            }
            __syncthreads();
            int row = tid & 63, qq = tid >> 6;   // 8 col-streams
            #pragma unroll 1
            for (int blk = 0; blk < 8; blk++) {
                int cb = blk*8;
                if (tid < NB) {   // serial solve within 8-column block
                    #pragma unroll
                    for (int jj = 0; jj < 8; jj++) {
                        int j = cb + jj;
                        float a = Bs[tid][j];
                        for (int c = cb; c < j; c++) a -= Bs[tid][c]*Ld[j][c];
                        Bs[tid][j] = a * dinv[j];
                    }
                }
                __syncthreads();
                if (blk < 7) {    // parallel update of later columns
                    float rb[8];
                    #pragma unroll
                    for (int c = 0; c < 8; c++) rb[c] = Bs[row][cb+c];
                    for (int j = cb+8+qq; j < NB; j += 8) {
                        float s = 0.f;
                        #pragma unroll
                        for (int c = 0; c < 8; c++) s += rb[c]*Ld[j][cb+c];
                        Bs[row][j] -= s;
                    }
                    __syncthreads();
                }
            }
            for (int t2 = tid; t2 < NB*16; t2 += NT) {
                int i = t2 >> 4, j4 = (t2 & 15) << 2;
                float4 v = make_float4(Bs[i][j4],Bs[i][j4+1],Bs[i][j4+2],Bs[i][j4+3]);
                *(float4*)&g_S[(r0+i)*MP + c0 + j4] = v;
            }
        }

        if (p < NPAN-1) {
            CLUSTER_SYNC();
            // --- SYRK trailing update, tiles distributed over cluster ------
            int T = NPAN-1-p;
            int ntiles = T*(T+1)/2;
            for (int t0 = rank; t0 < ntiles; t0 += CL) {
                int idx = t0, bi = 0;
                while (idx >= bi+1){ idx -= bi+1; bi++; }
                int bj = idx;
                int rI = (p+1+bi)*NB, rJ = (p+1+bj)*NB;
                for (int t2 = tid; t2 < NB*16; t2 += NT) {
                    int i = t2 >> 4, j4 = (t2 & 15) << 2;
                    float4 v = __ldcg((const float4*)&g_S[(rI+i)*MP + c0 + j4]);
                    Ld[i][j4]=v.x; Ld[i][j4+1]=v.y; Ld[i][j4+2]=v.z; Ld[i][j4+3]=v.w;
                }
                if (bi != bj) {
                    for (int t2 = tid; t2 < NB*16; t2 += NT) {
                        int i = t2 >> 4, j4 = (t2 & 15) << 2;
                        float4 v = __ldcg((const float4*)&g_S[(rJ+i)*MP + c0 + j4]);
                        Bs[i][j4]=v.x; Bs[i][j4+1]=v.y; Bs[i][j4+2]=v.z; Bs[i][j4+3]=v.w;
                    }
                }
                __syncthreads();
                float (*Lj)[NB+1] = (bi==bj) ? Ld : Bs;
                // 512 threads: 2 rows x 4 cols each
                int sx = tid & 15, sy = tid >> 4;
                float acc[2][4] = {};
                #pragma unroll 4
                for (int kk = 0; kk < NB; kk++) {
                    float av[2], bv[4];
                    av[0]=Ld[sy*2][kk]; av[1]=Ld[sy*2+1][kk];
                    #pragma unroll
                    for (int v2=0;v2<4;v2++) bv[v2]=Lj[sx*4+v2][kk];
                    #pragma unroll
                    for (int u=0;u<2;u++)
                        #pragma unroll
                        for (int v2=0;v2<4;v2++) acc[u][v2] += av[u]*bv[v2];
                }
                #pragma unroll
                for (int u=0;u<2;u++) {
                    float* ptr = &g_S[(rI+sy*2+u)*MP + rJ + sx*4];
                    float4 old = __ldcg((const float4*)ptr);
                    old.x -= acc[u][0]; old.y -= acc[u][1];
                    old.z -= acc[u][2]; old.w -= acc[u][3];
                    *(float4*)ptr = old;
                }
                __syncthreads();
            }
            CLUSTER_SYNC();
        }
    }

    // ---------------- epilogue: loss (rank 0) ------------------------------
    if (rank == 0) {
        if (tid < NB) dinv[tid] = logsum;
        __syncthreads();
        if (tid == 0) {
            float l = 0.f;
            for (int k2 = 0; k2 < NB; k2++) l += dinv[k2];   // logdet S
            double quad1 = -(double)s_quad;
            double ed = (double)e;
            double rTrv = __ldcg(&g_rTr);
            double ldD0v = __ldcg(&g_ldD0);
            double q0v  = __ldcg(&g_q0);
            double logdetV = (double)(n - (NQ0 + NQ1)) * log(ed) + ldD0v + (double)l;
            double quad = (rTrv - q0v - quad1) / ed;
            double loss = 0.5 * (double)n * 1.8378770664093454836
                        + 0.5 * logdetV + 0.5 * quad;
            out[0] = (float)loss;
        }
    }
}

// ---------------- host launcher --------------------------------------------
extern "C" void kernel_launch(void* const* d_in, const int* in_sizes, int n_in,
                              void* d_out, int out_size) {
    const float* y_true = (const float*)d_in[0];
    const float* y_pred = (const float*)d_in[1];
    const void*  z0     = d_in[2];
    const void*  z1     = d_in[3];
    const float* sig2e  = (const float*)d_in[4];
    const float* sig2bs = (const float*)d_in[5];
    float* out = (float*)d_out;
    int n = in_sizes[0];

    k_all<<<CL, NT>>>(y_true, y_pred, z0, z1, sig2e, sig2bs, out, n);
}

// round 12
// speedup vs baseline: 1.3209x; 1.0040x over previous
#include <cuda_runtime.h>
#include <math.h>

#define NQ0 1000
#define NQ1 500
#define MP  512          // padded+bordered Schur dim: 500 S + 11 identity + 1 border(u)
#define G0P 1024
#define NB  64
#define NPAN (MP/NB)     // 8
#define CL  8            // cluster size
#define NT  512          // threads per CTA (16 warps) — empirically optimal
#define GT  (CL*NT)      // 4096 cluster-wide threads
#define NMAX 8192
#define UROW (MP-1)      // 511: border row holding u

// ---------------- device scratch ----------------
static __device__ float g_S[MP*MP];
static __device__ float g_n0[G0P], g_s0[G0P], g_w0[G0P], g_ws0[G0P];
static __device__ float g_n1[MP],  g_s1[MP];
static __device__ int   g_off[G0P+1];
static __device__ int   g_cur[G0P];
static __device__ unsigned short g_csr[NMAX];
static __device__ int   g_i0[NMAX], g_i1[NMAX];
static __device__ double g_rTr, g_ldD0, g_q0;

// barrier.cluster.arrive has RELEASE semantics (PTX default), wait has ACQUIRE:
// all cross-CTA traffic here is __ldcg / atomics (L2), so no __threadfence needed.
#define CLUSTER_SYNC() do { \
    asm volatile("barrier.cluster.arrive.aligned;" ::: "memory"); \
    asm volatile("barrier.cluster.wait.aligned;"   ::: "memory"); } while (0)

// =================== single fused cluster kernel ===========================
__global__ void __cluster_dims__(CL,1,1) __launch_bounds__(NT,1)
k_all(const float* __restrict__ yt, const float* __restrict__ yp,
      const void* z0, const void* z1,
      const float* __restrict__ sig2e, const float* __restrict__ sig2bs,
      float* __restrict__ out, int n)
{
    __shared__ float Ld[NB][NB+1];      // diag factor / SYRK Li tile
    __shared__ float Bs[NB][NB+1];      // TRSM tile / SYRK Lj tile
    __shared__ float colbuf[NB][49];    // eliminated cols (3 per rank-4 batch x16)
    __shared__ float dinv[NB];
    __shared__ float s_quad;
    __shared__ double sred[3][16];
    __shared__ int   wsum[16];
    __shared__ int   s_is64;

    int rank = blockIdx.x;
    int tid  = threadIdx.x;
    int lane = tid & 31, wid = tid >> 5;
    int gt   = rank * NT + tid;

    // ---------------- A: zero scratch + detect index width -----------------
    {
        float4* S4 = (float4*)g_S;
        const float4 z4 = make_float4(0.f,0.f,0.f,0.f);
        for (int i = gt; i < (MP*MP)/4; i += GT) S4[i] = z4;
        if (gt < G0P) { g_n0[gt]=0.f; g_s0[gt]=0.f; g_cur[gt]=0; }
        if (gt < MP)  { g_n1[gt]=0.f; g_s1[gt]=0.f; }
        if (gt == 0)  { g_rTr=0.0; g_ldD0=0.0; g_q0=0.0; g_off[0]=0; }
        if (wid == 0) {
            const unsigned int* w = (const unsigned int*)z0;
            unsigned int v = w[1+2*lane] | w[65+2*lane];
            unsigned int nz = __ballot_sync(0xffffffffu, v != 0u);
            if (lane == 0) s_is64 = (nz == 0u);
        }
    }
    CLUSTER_SYNC();
    int is64 = s_is64;

    // ---------------- B: scatter (counts, sums, rTr) -----------------------
    double rtr = 0.0;
    for (int i = gt; i < n && i < NMAX; i += GT) {
        float r = yt[i] - yp[i];
        int a, b;
        if (is64) { a=(int)((const long long*)z0)[i]; b=(int)((const long long*)z1)[i]; }
        else      { a=((const int*)z0)[i];            b=((const int*)z1)[i]; }
        if ((unsigned)a < (unsigned)NQ0 && (unsigned)b < (unsigned)NQ1) {
            g_i0[i]=a; g_i1[i]=b;
            atomicAdd(&g_n0[a],1.f); atomicAdd(&g_s0[a],r);
            atomicAdd(&g_n1[b],1.f); atomicAdd(&g_s1[b],r);
            rtr += (double)r * (double)r;
        } else { g_i0[i]=0; g_i1[i]=0; }
    }
    #pragma unroll
    for (int o=16;o;o>>=1) rtr += __shfl_down_sync(0xffffffffu, rtr, o);
    if (lane==0) sred[0][wid] = rtr;
    __syncthreads();
    if (tid==0){ double s=0; for (int k2=0;k2<16;k2++) s+=sred[0][k2]; atomicAdd(&g_rTr,s); }
    CLUSTER_SYNC();

    // ---------------- C: prep + prefix scan (rank 0) -----------------------
    float e = sig2e[0], b0 = sig2bs[0], b1 = sig2bs[1];
    float sqb1 = sqrtf(b1);
    {
        double ld = 0.0, q = 0.0;
        for (int i = gt; i < G0P + MP; i += GT) {
            if (i < G0P) {
                float cnt = __ldcg(&g_n0[i]);
                float s0v = __ldcg(&g_s0[i]);
                float d0 = e + b0*cnt, w = 1.f/d0;
                g_w0[i] = w; g_ws0[i] = s0v*w;
                if (i < NQ0) {
                    ld += log((double)d0);
                    q  += (double)b0*(double)s0v*(double)s0v*(double)w;
                }
            } else {
                int j = i - G0P;
                if (j < NQ1) {
                    g_S[j*MP+j] = e + b1*__ldcg(&g_n1[j]);
                    g_S[UROW*MP+j] = sqb1*__ldcg(&g_s1[j]);   // border row = u
                } else if (j < UROW) g_S[j*MP+j] = 1.f;       // identity padding
            }
        }
        #pragma unroll
        for (int o=16;o;o>>=1) {
            ld += __shfl_down_sync(0xffffffffu, ld, o);
            q  += __shfl_down_sync(0xffffffffu, q,  o);
        }
        if (lane==0) { sred[1][wid]=ld; sred[2][wid]=q; }
        __syncthreads();
        if (tid==0) {
            double a1=0,a2=0;
            for (int k2=0;k2<16;k2++){a1+=sred[1][k2];a2+=sred[2][k2];}
            atomicAdd(&g_ldD0,a1); atomicAdd(&g_q0,a2);
        }
    }
    if (rank == 0) {   // scan: 512 threads x 2 elements
        int base = tid*2;
        int c0i=(int)__ldcg(&g_n0[base]), c1i=(int)__ldcg(&g_n0[base+1]);
        int s = c0i+c1i;
        int v = s;
        #pragma unroll
        for (int o=1;o<32;o<<=1){int y=__shfl_up_sync(0xffffffffu,v,o); if(lane>=o)v+=y;}
        if (lane==31) wsum[wid]=v;
        __syncthreads();
        if (wid==0 && lane<16){
            int wv=wsum[lane];
            #pragma unroll
            for (int o=1;o<16;o<<=1){int y=__shfl_up_sync(0xffffu,wv,o); if(lane>=o)wv+=y;}
            wsum[lane]=wv;
        }
        __syncthreads();
        int excl = v - s + (wid ? wsum[wid-1] : 0);
        g_off[base+1]=excl+c0i;
        g_off[base+2]=excl+s;
    }
    CLUSTER_SYNC();

    // ---------------- D: csr build + u correction --------------------------
    {
        float ucoef = -sqb1 * b0;
        for (int i = gt; i < n && i < NMAX; i += GT) {
            int a = g_i0[i], b = g_i1[i];
            int ppos = atomicAdd(&g_cur[a], 1);
            g_csr[__ldcg(&g_off[a]) + ppos] = (unsigned short)b;
            atomicAdd(&g_S[UROW*MP + b], ucoef * __ldcg(&g_ws0[a]));
        }
    }
    CLUSTER_SYNC();

    // ---------------- E: pairs (sparse C^T D0^{-1} C, shfl broadcast) ------
    {
        int gw = rank*16 + wid;
        for (int g = gw; g < NQ0; g += CL*16) {
            int lo  = __ldcg(&g_off[g]);
            int len = __ldcg(&g_off[g+1]) - lo;
            if (!len) continue;
            float coef = -b0*b1*__ldcg(&g_w0[g]);
            if (len <= 32) {
                int bv = 0;
                if (lane < len) bv = (int)__ldcg(&g_csr[lo + lane]);
                for (int ia = 0; ia < len; ia++) {
                    int a = __shfl_sync(0xffffffffu, bv, ia);
                    if (lane < len) atomicAdd(&g_S[a*MP + bv], coef);
                }
            } else {
                for (int ia = 0; ia < len; ia++) {
                    int a = (int)__ldcg(&g_csr[lo + ia]);
                    float* rowp = &g_S[a*MP];
                    for (int ib = lane; ib < len; ib += 32) {
                        int b = (int)__ldcg(&g_csr[lo + ib]);
                        atomicAdd(&rowp[b], coef);
                    }
                }
            }
        }
    }
    CLUSTER_SYNC();

    // ---------------- F: bordered blocked Cholesky (rank-4 batches) --------
    float logsum = 0.f;   // tid<64: per-diag-slot sum of log(pivot)
    int tx = lane, ty = wid;   // 16 row-streams x 32 col-lanes

    for (int p = 0; p < NPAN; p++) {
        int c0 = p*NB;
        // load diag block (float4, L1-bypass)
        for (int t2 = tid; t2 < NB*16; t2 += NT) {
            int i = t2 >> 4, j4 = (t2 & 15) << 2;
            float4 v = __ldcg((const float4*)&g_S[(c0+i)*MP + c0 + j4]);
            Ld[i][j4]=v.x; Ld[i][j4+1]=v.y; Ld[i][j4+2]=v.z; Ld[i][j4+3]=v.w;
        }
        __syncthreads();

        // --- rank-4 deferred-scaling elimination: 16 batches, 1 barrier each
        #pragma unroll 1
        for (int bb = 0; bb < 16; bb++) {
            int k = bb*4;
            // 4x4 head (redundant in all threads): LDL^T of leading block
            float A00=Ld[k][k];
            float A10=Ld[k+1][k], A11=Ld[k+1][k+1];
            float A20=Ld[k+2][k], A21=Ld[k+2][k+1], A22=Ld[k+2][k+2];
            float A30=Ld[k+3][k], A31=Ld[k+3][k+1], A32=Ld[k+3][k+2], A33=Ld[k+3][k+3];
            float r0=__frcp_rn(A00);
            float t10=A10*r0;
            float d1=A11-A10*t10;  float r1=__frcp_rn(d1);
            float t20=A20*r0;
            float bp21=A21-A20*t10; float t21=bp21*r1;
            float d2=A22-A20*t20-bp21*t21; float r2=__frcp_rn(d2);
            float t30=A30*r0;
            float bp31=A31-A30*t10; float t31=bp31*r1;
            float bp32=A32-A30*t20-bp31*t21; float t32=bp32*r2;
            float d3=A33-A30*t30-bp31*t31-bp32*t32; float r3=__frcp_rn(d3);
            // per-thread column multipliers (j as lower-triangle row index)
            int j0=k+4+tx, j1=j0+32;
            float c00=0.f,c01=0.f,c02=0.f,c03=0.f;
            float c10=0.f,c11=0.f,c12=0.f,c13=0.f;
            if (j0 < NB) {
                float a0=Ld[j0][k],a1=Ld[j0][k+1],a2=Ld[j0][k+2],a3=Ld[j0][k+3];
                float b1v=a1-a0*t10;
                float b2v=a2-a0*t20-b1v*t21;
                float b3v=a3-a0*t30-b1v*t31-b2v*t32;
                c00=a0*r0; c01=b1v*r1; c02=b2v*r2; c03=b3v*r3;
            }
            if (j1 < NB) {
                float a0=Ld[j1][k],a1=Ld[j1][k+1],a2=Ld[j1][k+2],a3=Ld[j1][k+3];
                float b1v=a1-a0*t10;
                float b2v=a2-a0*t20-b1v*t21;
                float b3v=a3-a0*t30-b1v*t31-b2v*t32;
                c10=a0*r0; c11=b1v*r1; c12=b2v*r2; c13=b3v*r3;
            }
            for (int i = k+1+ty; i < NB; i += 16) {
                float a0=Ld[i][k],a1=Ld[i][k+1],a2=Ld[i][k+2],a3=Ld[i][k+3];
                float b1v=a1-a0*t10;
                float b2v=a2-a0*t20-b1v*t21;
                float b3v=a3-a0*t30-b1v*t31-b2v*t32;
                if (tx == 0) {
                    colbuf[i][bb*3]   = b1v;
                    colbuf[i][bb*3+1] = b2v;
                    colbuf[i][bb*3+2] = b3v;
                }
                if (j0 <= i) Ld[i][j0] -= a0*c00 + b1v*c01 + b2v*c02 + b3v*c03;
                if (j1 <= i) Ld[i][j1] -= a0*c10 + b1v*c11 + b2v*c12 + b3v*c13;
            }
            __syncthreads();
        }
        // restore eliminated columns (final unscaled values incl. diagonals)
        for (int t2 = tid; t2 < NB*16; t2 += NT) {
            int i = t2 >> 4, bb = t2 & 15;
            int jb = bb*4, c = bb*3;
            float v1 = colbuf[i][c], v2 = colbuf[i][c+1], v3 = colbuf[i][c+2];
            if (i >= jb+1) Ld[i][jb+1] = v1;
            if (i >= jb+2) Ld[i][jb+2] = v2;
            if (i >= jb+3) Ld[i][jb+3] = v3;
        }
        __syncthreads();
        // scaling: pivots -> dinv/log; scale strictly-lower columns
        if (tid < NB) {
            float v = Ld[tid][tid];
            if (p == NPAN-1 && tid == NB-1) { s_quad = v; dinv[tid] = 1.f; }
            else { dinv[tid] = rsqrtf(v); logsum += logf(v); }   // log d_k
        }
        __syncthreads();
        for (int t2 = tid; t2 < NB*NB; t2 += NT) {
            int i = t2 >> 6, j = t2 & 63;
            if (i > j) Ld[i][j] *= dinv[j];
        }
        __syncthreads();

        // --- blocked right-looking TRSM: CTA `rank` owns row panel p+1+rank
        int r = p + 1 + rank;
        if (r < NPAN) {
            int r0 = r*NB;
            for (int t2 = tid; t2 < NB*16; t2 += NT) {
                int i = t2 >> 4, j4 = (t2 & 15) << 2;
                float4 v = __ldcg((const float4*)&g_S[(r0+i)*MP + c0 + j4]);
                Bs[i][j4]=v.x; Bs[i][j4+1]=v.y; Bs[i][j4+2]=v.z; Bs[i][j4+3]=v.w;
            }
            __syncthreads();
            int row = tid & 63, qq = tid >> 6;   // 8 col-streams
            #pragma unroll 1
            for (int blk = 0; blk < 8; blk++) {
                int cb = blk*8;
                if (tid < NB) {   // serial solve within 8-column block
                    #pragma unroll
                    for (int jj = 0; jj < 8; jj++) {
                        int j = cb + jj;
                        float a = Bs[tid][j];
                        for (int c = cb; c < j; c++) a -= Bs[tid][c]*Ld[j][c];
                        Bs[tid][j] = a * dinv[j];
                    }
                }
                __syncthreads();
                if (blk < 7) {    // parallel update of later columns
                    float rb[8];
                    #pragma unroll
                    for (int c = 0; c < 8; c++) rb[c] = Bs[row][cb+c];
                    for (int j = cb+8+qq; j < NB; j += 8) {
                        float s = 0.f;
                        #pragma unroll
                        for (int c = 0; c < 8; c++) s += rb[c]*Ld[j][cb+c];
                        Bs[row][j] -= s;
                    }
                    __syncthreads();
                }
            }
            for (int t2 = tid; t2 < NB*16; t2 += NT) {
                int i = t2 >> 4, j4 = (t2 & 15) << 2;
                float4 v = make_float4(Bs[i][j4],Bs[i][j4+1],Bs[i][j4+2],Bs[i][j4+3]);
                *(float4*)&g_S[(r0+i)*MP + c0 + j4] = v;
            }
        }

        if (p < NPAN-1) {
            CLUSTER_SYNC();
            // --- SYRK trailing update, tiles distributed over cluster ------
            int T = NPAN-1-p;
            int ntiles = T*(T+1)/2;
            for (int t0 = rank; t0 < ntiles; t0 += CL) {
                int idx = t0, bi = 0;
                while (idx >= bi+1){ idx -= bi+1; bi++; }
                int bj = idx;
                int rI = (p+1+bi)*NB, rJ = (p+1+bj)*NB;
                for (int t2 = tid; t2 < NB*16; t2 += NT) {
                    int i = t2 >> 4, j4 = (t2 & 15) << 2;
                    float4 v = __ldcg((const float4*)&g_S[(rI+i)*MP + c0 + j4]);
                    Ld[i][j4]=v.x; Ld[i][j4+1]=v.y; Ld[i][j4+2]=v.z; Ld[i][j4+3]=v.w;
                }
                if (bi != bj) {
                    for (int t2 = tid; t2 < NB*16; t2 += NT) {
                        int i = t2 >> 4, j4 = (t2 & 15) << 2;
                        float4 v = __ldcg((const float4*)&g_S[(rJ+i)*MP + c0 + j4]);
                        Bs[i][j4]=v.x; Bs[i][j4+1]=v.y; Bs[i][j4+2]=v.z; Bs[i][j4+3]=v.w;
                    }
                }
                __syncthreads();
                float (*Lj)[NB+1] = (bi==bj) ? Ld : Bs;
                // 512 threads: 2 rows x 4 cols each
                int sx = tid & 15, sy = tid >> 4;
                float acc[2][4] = {};
                #pragma unroll 4
                for (int kk = 0; kk < NB; kk++) {
                    float av[2], bv[4];
                    av[0]=Ld[sy*2][kk]; av[1]=Ld[sy*2+1][kk];
                    #pragma unroll
                    for (int v2=0;v2<4;v2++) bv[v2]=Lj[sx*4+v2][kk];
                    #pragma unroll
                    for (int u=0;u<2;u++)
                        #pragma unroll
                        for (int v2=0;v2<4;v2++) acc[u][v2] += av[u]*bv[v2];
                }
                #pragma unroll
                for (int u=0;u<2;u++) {
                    float* ptr = &g_S[(rI+sy*2+u)*MP + rJ + sx*4];
                    float4 old = __ldcg((const float4*)ptr);
                    old.x -= acc[u][0]; old.y -= acc[u][1];
                    old.z -= acc[u][2]; old.w -= acc[u][3];
                    *(float4*)ptr = old;
                }
                __syncthreads();
            }
            CLUSTER_SYNC();
        }
    }

    // ---------------- epilogue: loss (rank 0) ------------------------------
    if (rank == 0) {
        if (tid < NB) dinv[tid] = logsum;
        __syncthreads();
        if (tid == 0) {
            float l = 0.f;
            for (int k2 = 0; k2 < NB; k2++) l += dinv[k2];   // logdet S
            double quad1 = -(double)s_quad;
            double ed = (double)e;
            double rTrv = __ldcg(&g_rTr);
            double ldD0v = __ldcg(&g_ldD0);
            double q0v  = __ldcg(&g_q0);
            double logdetV = (double)(n - (NQ0 + NQ1)) * log(ed) + ldD0v + (double)l;
            double quad = (rTrv - q0v - quad1) / ed;
            double loss = 0.5 * (double)n * 1.8378770664093454836
                        + 0.5 * logdetV + 0.5 * quad;
            out[0] = (float)loss;
        }
    }
}

// ---------------- host launcher --------------------------------------------
extern "C" void kernel_launch(void* const* d_in, const int* in_sizes, int n_in,
                              void* d_out, int out_size) {
    const float* y_true = (const float*)d_in[0];
    const float* y_pred = (const float*)d_in[1];
    const void*  z0     = d_in[2];
    const void*  z1     = d_in[3];
    const float* sig2e  = (const float*)d_in[4];
    const float* sig2bs = (const float*)d_in[5];
    float* out = (float*)d_out;
    int n = in_sizes[0];

    k_all<<<CL, NT>>>(y_true, y_pred, z0, z1, sig2e, sig2bs, out, n);
}

// round 13
// speedup vs baseline: 1.3265x; 1.0042x over previous
#include <cuda_runtime.h>
#include <math.h>

#define NQ0 1000
#define NQ1 500
#define MP  512          // padded+bordered Schur dim: 500 S + 11 identity + 1 border(u)
#define G0P 1024
#define NB  64
#define NPAN (MP/NB)     // 8
#define CL  8            // cluster size
#define NT  512          // threads per CTA (16 warps) — empirically optimal
#define GT  (CL*NT)      // 4096 cluster-wide threads
#define NMAX 8192
#define UROW (MP-1)      // 511: border row holding u

// ---------------- device scratch ----------------
static __device__ float g_S[MP*MP];
static __device__ float g_n0[G0P], g_s0[G0P], g_w0[G0P], g_ws0[G0P];
static __device__ float g_n1[MP],  g_s1[MP];
static __device__ int   g_off[G0P+1];
static __device__ int   g_cur[G0P];
static __device__ unsigned short g_csr[NMAX];
static __device__ int   g_i0[NMAX], g_i1[NMAX];
static __device__ double g_rTr, g_ldD0, g_q0;

// barrier.cluster.arrive has RELEASE semantics (PTX default), wait has ACQUIRE:
// all cross-CTA traffic here is __ldcg / atomics (L2), so no __threadfence needed.
#define CLUSTER_SYNC() do { \
    asm volatile("barrier.cluster.arrive.aligned;" ::: "memory"); \
    asm volatile("barrier.cluster.wait.aligned;"   ::: "memory"); } while (0)

// =================== single fused cluster kernel ===========================
__global__ void __cluster_dims__(CL,1,1) __launch_bounds__(NT,1)
k_all(const float* __restrict__ yt, const float* __restrict__ yp,
      const void* z0, const void* z1,
      const float* __restrict__ sig2e, const float* __restrict__ sig2bs,
      float* __restrict__ out, int n)
{
    __shared__ float Ld[NB][NB+1];      // diag factor / SYRK Li tile
    __shared__ float Bs[NB][NB+1];      // TRSM tile / SYRK Lj tile
    __shared__ float colbuf[NB][49];    // eliminated cols (3 per rank-4 batch x16)
    __shared__ float dinv[NB];
    __shared__ float s_quad;
    __shared__ double sred[3][16];
    __shared__ int   wsum[16];
    __shared__ int   s_is64;

    int rank = blockIdx.x;
    int tid  = threadIdx.x;
    int lane = tid & 31, wid = tid >> 5;
    int gt   = rank * NT + tid;

    // ---------------- A: zero scratch + detect index width -----------------
    {
        float4* S4 = (float4*)g_S;
        const float4 z4 = make_float4(0.f,0.f,0.f,0.f);
        for (int i = gt; i < (MP*MP)/4; i += GT) S4[i] = z4;
        if (gt < G0P) { g_n0[gt]=0.f; g_s0[gt]=0.f; g_cur[gt]=0; }
        if (gt < MP)  { g_n1[gt]=0.f; g_s1[gt]=0.f; }
        if (gt == 0)  { g_rTr=0.0; g_ldD0=0.0; g_q0=0.0; g_off[0]=0; }
        if (wid == 0) {
            const unsigned int* w = (const unsigned int*)z0;
            unsigned int v = w[1+2*lane] | w[65+2*lane];
            unsigned int nz = __ballot_sync(0xffffffffu, v != 0u);
            if (lane == 0) s_is64 = (nz == 0u);
        }
    }
    CLUSTER_SYNC();
    int is64 = s_is64;

    // ---------------- B: scatter (counts, sums, rTr) -----------------------
    double rtr = 0.0;
    for (int i = gt; i < n && i < NMAX; i += GT) {
        float r = yt[i] - yp[i];
        int a, b;
        if (is64) { a=(int)((const long long*)z0)[i]; b=(int)((const long long*)z1)[i]; }
        else      { a=((const int*)z0)[i];            b=((const int*)z1)[i]; }
        if ((unsigned)a < (unsigned)NQ0 && (unsigned)b < (unsigned)NQ1) {
            g_i0[i]=a; g_i1[i]=b;
            atomicAdd(&g_n0[a],1.f); atomicAdd(&g_s0[a],r);
            atomicAdd(&g_n1[b],1.f); atomicAdd(&g_s1[b],r);
            rtr += (double)r * (double)r;
        } else { g_i0[i]=0; g_i1[i]=0; }
    }
    #pragma unroll
    for (int o=16;o;o>>=1) rtr += __shfl_down_sync(0xffffffffu, rtr, o);
    if (lane==0) sred[0][wid] = rtr;
    __syncthreads();
    if (tid==0){ double s=0; for (int k2=0;k2<16;k2++) s+=sred[0][k2]; atomicAdd(&g_rTr,s); }
    CLUSTER_SYNC();

    // ---------------- C: prep + prefix scan (rank 0) -----------------------
    float e = sig2e[0], b0 = sig2bs[0], b1 = sig2bs[1];
    float sqb1 = sqrtf(b1);
    {
        double ld = 0.0, q = 0.0;
        for (int i = gt; i < G0P + MP; i += GT) {
            if (i < G0P) {
                float cnt = __ldcg(&g_n0[i]);
                float s0v = __ldcg(&g_s0[i]);
                float d0 = e + b0*cnt, w = 1.f/d0;
                g_w0[i] = w; g_ws0[i] = s0v*w;
                if (i < NQ0) {
                    ld += log((double)d0);
                    q  += (double)b0*(double)s0v*(double)s0v*(double)w;
                }
            } else {
                int j = i - G0P;
                if (j < NQ1) {
                    g_S[j*MP+j] = e + b1*__ldcg(&g_n1[j]);
                    g_S[UROW*MP+j] = sqb1*__ldcg(&g_s1[j]);   // border row = u
                } else if (j < UROW) g_S[j*MP+j] = 1.f;       // identity padding
            }
        }
        #pragma unroll
        for (int o=16;o;o>>=1) {
            ld += __shfl_down_sync(0xffffffffu, ld, o);
            q  += __shfl_down_sync(0xffffffffu, q,  o);
        }
        if (lane==0) { sred[1][wid]=ld; sred[2][wid]=q; }
        __syncthreads();
        if (tid==0) {
            double a1=0,a2=0;
            for (int k2=0;k2<16;k2++){a1+=sred[1][k2];a2+=sred[2][k2];}
            atomicAdd(&g_ldD0,a1); atomicAdd(&g_q0,a2);
        }
    }
    if (rank == 0) {   // scan: 512 threads x 2 elements
        int base = tid*2;
        int c0i=(int)__ldcg(&g_n0[base]), c1i=(int)__ldcg(&g_n0[base+1]);
        int s = c0i+c1i;
        int v = s;
        #pragma unroll
        for (int o=1;o<32;o<<=1){int y=__shfl_up_sync(0xffffffffu,v,o); if(lane>=o)v+=y;}
        if (lane==31) wsum[wid]=v;
        __syncthreads();
        if (wid==0 && lane<16){
            int wv=wsum[lane];
            #pragma unroll
            for (int o=1;o<16;o<<=1){int y=__shfl_up_sync(0xffffu,wv,o); if(lane>=o)wv+=y;}
            wsum[lane]=wv;
        }
        __syncthreads();
        int excl = v - s + (wid ? wsum[wid-1] : 0);
        g_off[base+1]=excl+c0i;
        g_off[base+2]=excl+s;
    }
    CLUSTER_SYNC();

    // ---------------- D: csr build + u correction --------------------------
    {
        float ucoef = -sqb1 * b0;
        for (int i = gt; i < n && i < NMAX; i += GT) {
            int a = g_i0[i], b = g_i1[i];
            int ppos = atomicAdd(&g_cur[a], 1);
            g_csr[__ldcg(&g_off[a]) + ppos] = (unsigned short)b;
            atomicAdd(&g_S[UROW*MP + b], ucoef * __ldcg(&g_ws0[a]));
        }
    }
    CLUSTER_SYNC();

    // ---------------- E: pairs (sparse C^T D0^{-1} C, shfl broadcast) ------
    {
        int gw = rank*16 + wid;
        for (int g = gw; g < NQ0; g += CL*16) {
            int lo  = __ldcg(&g_off[g]);
            int len = __ldcg(&g_off[g+1]) - lo;
            if (!len) continue;
            float coef = -b0*b1*__ldcg(&g_w0[g]);
            if (len <= 32) {
                int bv = 0;
                if (lane < len) bv = (int)__ldcg(&g_csr[lo + lane]);
                for (int ia = 0; ia < len; ia++) {
                    int a = __shfl_sync(0xffffffffu, bv, ia);
                    if (lane < len) atomicAdd(&g_S[a*MP + bv], coef);
                }
            } else {
                for (int ia = 0; ia < len; ia++) {
                    int a = (int)__ldcg(&g_csr[lo + ia]);
                    float* rowp = &g_S[a*MP];
                    for (int ib = lane; ib < len; ib += 32) {
                        int b = (int)__ldcg(&g_csr[lo + ib]);
                        atomicAdd(&rowp[b], coef);
                    }
                }
            }
        }
    }
    CLUSTER_SYNC();

    // ---------------- F: bordered blocked Cholesky (rank-4 batches) --------
    float logsum = 0.f;   // tid<64: per-diag-slot sum of log(pivot)
    int tx = lane, ty = wid;   // 16 row-streams x 32 col-lanes

    for (int p = 0; p < NPAN; p++) {
        int c0 = p*NB;
        // load diag block (float4, L1-bypass)
        for (int t2 = tid; t2 < NB*16; t2 += NT) {
            int i = t2 >> 4, j4 = (t2 & 15) << 2;
            float4 v = __ldcg((const float4*)&g_S[(c0+i)*MP + c0 + j4]);
            Ld[i][j4]=v.x; Ld[i][j4+1]=v.y; Ld[i][j4+2]=v.z; Ld[i][j4+3]=v.w;
        }
        __syncthreads();

        // --- rank-4 deferred-scaling elimination: 16 batches, 1 barrier each
        #pragma unroll 1
        for (int bb = 0; bb < 16; bb++) {
            int k = bb*4;
            // 4x4 head (redundant in all threads): LDL^T of leading block
            float A00=Ld[k][k];
            float A10=Ld[k+1][k], A11=Ld[k+1][k+1];
            float A20=Ld[k+2][k], A21=Ld[k+2][k+1], A22=Ld[k+2][k+2];
            float A30=Ld[k+3][k], A31=Ld[k+3][k+1], A32=Ld[k+3][k+2], A33=Ld[k+3][k+3];
            float r0=__frcp_rn(A00);
            float t10=A10*r0;
            float d1=A11-A10*t10;  float r1=__frcp_rn(d1);
            float t20=A20*r0;
            float bp21=A21-A20*t10; float t21=bp21*r1;
            float d2=A22-A20*t20-bp21*t21; float r2=__frcp_rn(d2);
            float t30=A30*r0;
            float bp31=A31-A30*t10; float t31=bp31*r1;
            float bp32=A32-A30*t20-bp31*t21; float t32=bp32*r2;
            float d3=A33-A30*t30-bp31*t31-bp32*t32; float r3=__frcp_rn(d3);
            // per-thread column multipliers (j as lower-triangle row index)
            int j0=k+4+tx, j1=j0+32;
            float c00=0.f,c01=0.f,c02=0.f,c03=0.f;
            float c10=0.f,c11=0.f,c12=0.f,c13=0.f;
            if (j0 < NB) {
                float a0=Ld[j0][k],a1=Ld[j0][k+1],a2=Ld[j0][k+2],a3=Ld[j0][k+3];
                float b1v=a1-a0*t10;
                float b2v=a2-a0*t20-b1v*t21;
                float b3v=a3-a0*t30-b1v*t31-b2v*t32;
                c00=a0*r0; c01=b1v*r1; c02=b2v*r2; c03=b3v*r3;
            }
            if (j1 < NB) {
                float a0=Ld[j1][k],a1=Ld[j1][k+1],a2=Ld[j1][k+2],a3=Ld[j1][k+3];
                float b1v=a1-a0*t10;
                float b2v=a2-a0*t20-b1v*t21;
                float b3v=a3-a0*t30-b1v*t31-b2v*t32;
                c10=a0*r0; c11=b1v*r1; c12=b2v*r2; c13=b3v*r3;
            }
            for (int i = k+1+ty; i < NB; i += 16) {
                float a0=Ld[i][k],a1=Ld[i][k+1],a2=Ld[i][k+2],a3=Ld[i][k+3];
                float b1v=a1-a0*t10;
                float b2v=a2-a0*t20-b1v*t21;
                float b3v=a3-a0*t30-b1v*t31-b2v*t32;
                if (tx == 0) {
                    colbuf[i][bb*3]   = b1v;
                    colbuf[i][bb*3+1] = b2v;
                    colbuf[i][bb*3+2] = b3v;
                }
                if (j0 <= i) Ld[i][j0] -= a0*c00 + b1v*c01 + b2v*c02 + b3v*c03;
                if (j1 <= i) Ld[i][j1] -= a0*c10 + b1v*c11 + b2v*c12 + b3v*c13;
            }
            __syncthreads();
        }
        // restore eliminated columns (final unscaled values incl. diagonals)
        for (int t2 = tid; t2 < NB*16; t2 += NT) {
            int i = t2 >> 4, bb = t2 & 15;
            int jb = bb*4, c = bb*3;
            float v1 = colbuf[i][c], v2 = colbuf[i][c+1], v3 = colbuf[i][c+2];
            if (i >= jb+1) Ld[i][jb+1] = v1;
            if (i >= jb+2) Ld[i][jb+2] = v2;
            if (i >= jb+3) Ld[i][jb+3] = v3;
        }
        __syncthreads();
        // scaling: pivots -> dinv/log; scale strictly-lower columns
        if (tid < NB) {
            float v = Ld[tid][tid];
            if (p == NPAN-1 && tid == NB-1) { s_quad = v; dinv[tid] = 1.f; }
            else { dinv[tid] = rsqrtf(v); logsum += logf(v); }   // log d_k
        }
        __syncthreads();
        for (int t2 = tid; t2 < NB*NB; t2 += NT) {
            int i = t2 >> 6, j = t2 & 63;
            if (i > j) Ld[i][j] *= dinv[j];
        }
        __syncthreads();

        // --- blocked right-looking TRSM: CTA `rank` owns row panel p+1+rank
        int r = p + 1 + rank;
        if (r < NPAN) {
            int r0 = r*NB;
            for (int t2 = tid; t2 < NB*16; t2 += NT) {
                int i = t2 >> 4, j4 = (t2 & 15) << 2;
                float4 v = __ldcg((const float4*)&g_S[(r0+i)*MP + c0 + j4]);
                Bs[i][j4]=v.x; Bs[i][j4+1]=v.y; Bs[i][j4+2]=v.z; Bs[i][j4+3]=v.w;
            }
            __syncthreads();
            int row = tid & 63, qq = tid >> 6;   // 8 col-streams
            #pragma unroll 1
            for (int blk = 0; blk < 8; blk++) {
                int cb = blk*8;
                if (tid < NB) {   // serial solve within 8-column block
                    #pragma unroll
                    for (int jj = 0; jj < 8; jj++) {
                        int j = cb + jj;
                        float a = Bs[tid][j];
                        for (int c = cb; c < j; c++) a -= Bs[tid][c]*Ld[j][c];
                        Bs[tid][j] = a * dinv[j];
                    }
                }
                __syncthreads();
                if (blk < 7) {    // parallel update of later columns
                    float rb[8];
                    #pragma unroll
                    for (int c = 0; c < 8; c++) rb[c] = Bs[row][cb+c];
                    for (int j = cb+8+qq; j < NB; j += 8) {
                        float s = 0.f;
                        #pragma unroll
                        for (int c = 0; c < 8; c++) s += rb[c]*Ld[j][cb+c];
                        Bs[row][j] -= s;
                    }
                    __syncthreads();
                }
            }
            for (int t2 = tid; t2 < NB*16; t2 += NT) {
                int i = t2 >> 4, j4 = (t2 & 15) << 2;
                float4 v = make_float4(Bs[i][j4],Bs[i][j4+1],Bs[i][j4+2],Bs[i][j4+3]);
                *(float4*)&g_S[(r0+i)*MP + c0 + j4] = v;
            }
        }

        if (p < NPAN-1) {
            CLUSTER_SYNC();
            // --- SYRK trailing update, tiles distributed over cluster ------
            int T = NPAN-1-p;
            int ntiles = T*(T+1)/2;
            for (int t0 = rank; t0 < ntiles; t0 += CL) {
                int idx = t0, bi = 0;
                while (idx >= bi+1){ idx -= bi+1; bi++; }
                int bj = idx;
                int rI = (p+1+bi)*NB, rJ = (p+1+bj)*NB;
                for (int t2 = tid; t2 < NB*16; t2 += NT) {
                    int i = t2 >> 4, j4 = (t2 & 15) << 2;
                    float4 v = __ldcg((const float4*)&g_S[(rI+i)*MP + c0 + j4]);
                    Ld[i][j4]=v.x; Ld[i][j4+1]=v.y; Ld[i][j4+2]=v.z; Ld[i][j4+3]=v.w;
                }
                if (bi != bj) {
                    for (int t2 = tid; t2 < NB*16; t2 += NT) {
                        int i = t2 >> 4, j4 = (t2 & 15) << 2;
                        float4 v = __ldcg((const float4*)&g_S[(rJ+i)*MP + c0 + j4]);
                        Bs[i][j4]=v.x; Bs[i][j4+1]=v.y; Bs[i][j4+2]=v.z; Bs[i][j4+3]=v.w;
                    }
                }
                __syncthreads();
                float (*Lj)[NB+1] = (bi==bj) ? Ld : Bs;
                // 512 threads: 2 rows x 4 cols each
                int sx = tid & 15, sy = tid >> 4;
                float acc[2][4] = {};
                #pragma unroll 4
                for (int kk = 0; kk < NB; kk++) {
                    float av[2], bv[4];
                    av[0]=Ld[sy*2][kk]; av[1]=Ld[sy*2+1][kk];
                    #pragma unroll
                    for (int v2=0;v2<4;v2++) bv[v2]=Lj[sx*4+v2][kk];
                    #pragma unroll
                    for (int u=0;u<2;u++)
                        #pragma unroll
                        for (int v2=0;v2<4;v2++) acc[u][v2] += av[u]*bv[v2];
                }
                #pragma unroll
                for (int u=0;u<2;u++) {
                    float* ptr = &g_S[(rI+sy*2+u)*MP + rJ + sx*4];
                    float4 old = __ldcg((const float4*)ptr);
                    old.x -= acc[u][0]; old.y -= acc[u][1];
                    old.z -= acc[u][2]; old.w -= acc[u][3];
                    *(float4*)ptr = old;
                }
                __syncthreads();
            }
            CLUSTER_SYNC();
        }
    }

    // ---------------- epilogue: loss (rank 0) ------------------------------
    if (rank == 0) {
        if (tid < NB) dinv[tid] = logsum;
        __syncthreads();
        if (tid == 0) {
            float l = 0.f;
            for (int k2 = 0; k2 < NB; k2++) l += dinv[k2];   // logdet S
            double quad1 = -(double)s_quad;
            double ed = (double)e;
            double rTrv = __ldcg(&g_rTr);
            double ldD0v = __ldcg(&g_ldD0);
            double q0v  = __ldcg(&g_q0);
            double logdetV = (double)(n - (NQ0 + NQ1)) * log(ed) + ldD0v + (double)l;
            double quad = (rTrv - q0v - quad1) / ed;
            double loss = 0.5 * (double)n * 1.8378770664093454836
                        + 0.5 * logdetV + 0.5 * quad;
            out[0] = (float)loss;
        }
    }
}

// ---------------- host launcher --------------------------------------------
extern "C" void kernel_launch(void* const* d_in, const int* in_sizes, int n_in,
                              void* d_out, int out_size) {
    const float* y_true = (const float*)d_in[0];
    const float* y_pred = (const float*)d_in[1];
    const void*  z0     = d_in[2];
    const void*  z1     = d_in[3];
    const float* sig2e  = (const float*)d_in[4];
    const float* sig2bs = (const float*)d_in[5];
    float* out = (float*)d_out;
    int n = in_sizes[0];

    k_all<<<CL, NT>>>(y_true, y_pred, z0, z1, sig2e, sig2bs, out, n);
}

// round 14
// speedup vs baseline: 1.3267x; 1.0001x over previous
#include <cuda_runtime.h>
#include <math.h>

#define NQ0 1000
#define NQ1 500
#define MP  512          // padded+bordered Schur dim: 500 S + 11 identity + 1 border(u)
#define G0P 1024
#define NB  64
#define NPAN (MP/NB)     // 8
#define CL  8            // cluster size
#define NT  512          // threads per CTA (16 warps) — empirically optimal
#define GT  (CL*NT)      // 4096 cluster-wide threads
#define NMAX 8192
#define UROW (MP-1)      // 511: border row holding u

// ---------------- device scratch ----------------
static __device__ float g_S[MP*MP];
static __device__ float g_n0[G0P], g_s0[G0P], g_w0[G0P], g_ws0[G0P];
static __device__ float g_n1[MP],  g_s1[MP];
static __device__ int   g_off[G0P+1];
static __device__ int   g_cur[G0P];
static __device__ unsigned short g_csr[NMAX];
static __device__ int   g_i0[NMAX], g_i1[NMAX];
static __device__ double g_rTr, g_ldD0, g_q0;

// barrier.cluster.arrive has RELEASE semantics (PTX default), wait has ACQUIRE:
// all cross-CTA traffic here is __ldcg / atomics (L2), so no __threadfence needed.
#define CLUSTER_SYNC() do { \
    asm volatile("barrier.cluster.arrive.aligned;" ::: "memory"); \
    asm volatile("barrier.cluster.wait.aligned;"   ::: "memory"); } while (0)

// =================== single fused cluster kernel ===========================
__global__ void __cluster_dims__(CL,1,1) __launch_bounds__(NT,1)
k_all(const float* __restrict__ yt, const float* __restrict__ yp,
      const void* z0, const void* z1,
      const float* __restrict__ sig2e, const float* __restrict__ sig2bs,
      float* __restrict__ out, int n)
{
    __shared__ float Ld[NB][NB+1];      // diag factor / SYRK Li tile
    __shared__ float Bs[NB][NB+1];      // TRSM tile / SYRK Lj tile
    __shared__ float colbuf[NB][49];    // eliminated cols (3 per rank-4 batch x16)
    __shared__ float dinv[NB];
    __shared__ float s_quad;
    __shared__ double sred[3][16];
    __shared__ int   wsum[16];
    __shared__ int   s_is64;

    int rank = blockIdx.x;
    int tid  = threadIdx.x;
    int lane = tid & 31, wid = tid >> 5;
    int gt   = rank * NT + tid;

    // ---------------- A: zero scratch + detect index width -----------------
    {
        float4* S4 = (float4*)g_S;
        const float4 z4 = make_float4(0.f,0.f,0.f,0.f);
        for (int i = gt; i < (MP*MP)/4; i += GT) S4[i] = z4;
        if (gt < G0P) { g_n0[gt]=0.f; g_s0[gt]=0.f; g_cur[gt]=0; }
        if (gt < MP)  { g_n1[gt]=0.f; g_s1[gt]=0.f; }
        if (gt == 0)  { g_rTr=0.0; g_ldD0=0.0; g_q0=0.0; g_off[0]=0; }
        if (wid == 0) {
            const unsigned int* w = (const unsigned int*)z0;
            unsigned int v = w[1+2*lane] | w[65+2*lane];
            unsigned int nz = __ballot_sync(0xffffffffu, v != 0u);
            if (lane == 0) s_is64 = (nz == 0u);
        }
    }
    CLUSTER_SYNC();
    int is64 = s_is64;

    // ---------------- B: scatter (counts, sums, rTr) -----------------------
    double rtr = 0.0;
    for (int i = gt; i < n && i < NMAX; i += GT) {
        float r = yt[i] - yp[i];
        int a, b;
        if (is64) { a=(int)((const long long*)z0)[i]; b=(int)((const long long*)z1)[i]; }
        else      { a=((const int*)z0)[i];            b=((const int*)z1)[i]; }
        if ((unsigned)a < (unsigned)NQ0 && (unsigned)b < (unsigned)NQ1) {
            g_i0[i]=a; g_i1[i]=b;
            atomicAdd(&g_n0[a],1.f); atomicAdd(&g_s0[a],r);
            atomicAdd(&g_n1[b],1.f); atomicAdd(&g_s1[b],r);
            rtr += (double)r * (double)r;
        } else { g_i0[i]=0; g_i1[i]=0; }
    }
    #pragma unroll
    for (int o=16;o;o>>=1) rtr += __shfl_down_sync(0xffffffffu, rtr, o);
    if (lane==0) sred[0][wid] = rtr;
    __syncthreads();
    if (tid==0){ double s=0; for (int k2=0;k2<16;k2++) s+=sred[0][k2]; atomicAdd(&g_rTr,s); }
    CLUSTER_SYNC();

    // ---------------- C: prep + prefix scan (rank 0) -----------------------
    float e = sig2e[0], b0 = sig2bs[0], b1 = sig2bs[1];
    float sqb1 = sqrtf(b1);
    {
        double ld = 0.0, q = 0.0;
        for (int i = gt; i < G0P + MP; i += GT) {
            if (i < G0P) {
                float cnt = __ldcg(&g_n0[i]);
                float s0v = __ldcg(&g_s0[i]);
                float d0 = e + b0*cnt, w = 1.f/d0;
                g_w0[i] = w; g_ws0[i] = s0v*w;
                if (i < NQ0) {
                    ld += log((double)d0);
                    q  += (double)b0*(double)s0v*(double)s0v*(double)w;
                }
            } else {
                int j = i - G0P;
                if (j < NQ1) {
                    g_S[j*MP+j] = e + b1*__ldcg(&g_n1[j]);
                    g_S[UROW*MP+j] = sqb1*__ldcg(&g_s1[j]);   // border row = u
                } else if (j < UROW) g_S[j*MP+j] = 1.f;       // identity padding
            }
        }
        #pragma unroll
        for (int o=16;o;o>>=1) {
            ld += __shfl_down_sync(0xffffffffu, ld, o);
            q  += __shfl_down_sync(0xffffffffu, q,  o);
        }
        if (lane==0) { sred[1][wid]=ld; sred[2][wid]=q; }
        __syncthreads();
        if (tid==0) {
            double a1=0,a2=0;
            for (int k2=0;k2<16;k2++){a1+=sred[1][k2];a2+=sred[2][k2];}
            atomicAdd(&g_ldD0,a1); atomicAdd(&g_q0,a2);
        }
    }
    if (rank == 0) {   // scan: 512 threads x 2 elements
        int base = tid*2;
        int c0i=(int)__ldcg(&g_n0[base]), c1i=(int)__ldcg(&g_n0[base+1]);
        int s = c0i+c1i;
        int v = s;
        #pragma unroll
        for (int o=1;o<32;o<<=1){int y=__shfl_up_sync(0xffffffffu,v,o); if(lane>=o)v+=y;}
        if (lane==31) wsum[wid]=v;
        __syncthreads();
        if (wid==0 && lane<16){
            int wv=wsum[lane];
            #pragma unroll
            for (int o=1;o<16;o<<=1){int y=__shfl_up_sync(0xffffu,wv,o); if(lane>=o)wv+=y;}
            wsum[lane]=wv;
        }
        __syncthreads();
        int excl = v - s + (wid ? wsum[wid-1] : 0);
        g_off[base+1]=excl+c0i;
        g_off[base+2]=excl+s;
    }
    CLUSTER_SYNC();

    // ---------------- D: csr build + u correction --------------------------
    {
        float ucoef = -sqb1 * b0;
        for (int i = gt; i < n && i < NMAX; i += GT) {
            int a = g_i0[i], b = g_i1[i];
            int ppos = atomicAdd(&g_cur[a], 1);
            g_csr[__ldcg(&g_off[a]) + ppos] = (unsigned short)b;
            atomicAdd(&g_S[UROW*MP + b], ucoef * __ldcg(&g_ws0[a]));
        }
    }
    CLUSTER_SYNC();

    // ---------------- E: pairs (sparse C^T D0^{-1} C, shfl broadcast) ------
    {
        int gw = rank*16 + wid;
        for (int g = gw; g < NQ0; g += CL*16) {
            int lo  = __ldcg(&g_off[g]);
            int len = __ldcg(&g_off[g+1]) - lo;
            if (!len) continue;
            float coef = -b0*b1*__ldcg(&g_w0[g]);
            if (len <= 32) {
                int bv = 0;
                if (lane < len) bv = (int)__ldcg(&g_csr[lo + lane]);
                for (int ia = 0; ia < len; ia++) {
                    int a = __shfl_sync(0xffffffffu, bv, ia);
                    if (lane < len) atomicAdd(&g_S[a*MP + bv], coef);
                }
            } else {
                for (int ia = 0; ia < len; ia++) {
                    int a = (int)__ldcg(&g_csr[lo + ia]);
                    float* rowp = &g_S[a*MP];
                    for (int ib = lane; ib < len; ib += 32) {
                        int b = (int)__ldcg(&g_csr[lo + ib]);
                        atomicAdd(&rowp[b], coef);
                    }
                }
            }
        }
    }
    CLUSTER_SYNC();

    // ---------------- F: bordered blocked Cholesky (rank-4 batches) --------
    float logsum = 0.f;   // tid<64: per-diag-slot sum of log(pivot)
    int tx = lane, ty = wid;   // 16 row-streams x 32 col-lanes

    for (int p = 0; p < NPAN; p++) {
        int c0 = p*NB;
        // load diag block (float4, L1-bypass)
        for (int t2 = tid; t2 < NB*16; t2 += NT) {
            int i = t2 >> 4, j4 = (t2 & 15) << 2;
            float4 v = __ldcg((const float4*)&g_S[(c0+i)*MP + c0 + j4]);
            Ld[i][j4]=v.x; Ld[i][j4+1]=v.y; Ld[i][j4+2]=v.z; Ld[i][j4+3]=v.w;
        }
        __syncthreads();

        // --- rank-4 deferred-scaling elimination: 16 batches, 1 barrier each
        #pragma unroll 1
        for (int bb = 0; bb < 16; bb++) {
            int k = bb*4;
            // 4x4 head (redundant in all threads): LDL^T of leading block
            float A00=Ld[k][k];
            float A10=Ld[k+1][k], A11=Ld[k+1][k+1];
            float A20=Ld[k+2][k], A21=Ld[k+2][k+1], A22=Ld[k+2][k+2];
            float A30=Ld[k+3][k], A31=Ld[k+3][k+1], A32=Ld[k+3][k+2], A33=Ld[k+3][k+3];
            float r0=__frcp_rn(A00);
            float t10=A10*r0;
            float d1=A11-A10*t10;  float r1=__frcp_rn(d1);
            float t20=A20*r0;
            float bp21=A21-A20*t10; float t21=bp21*r1;
            float d2=A22-A20*t20-bp21*t21; float r2=__frcp_rn(d2);
            float t30=A30*r0;
            float bp31=A31-A30*t10; float t31=bp31*r1;
            float bp32=A32-A30*t20-bp31*t21; float t32=bp32*r2;
            float d3=A33-A30*t30-bp31*t31-bp32*t32; float r3=__frcp_rn(d3);
            // per-thread column multipliers (j as lower-triangle row index)
            int j0=k+4+tx, j1=j0+32;
            float c00=0.f,c01=0.f,c02=0.f,c03=0.f;
            float c10=0.f,c11=0.f,c12=0.f,c13=0.f;
            if (j0 < NB) {
                float a0=Ld[j0][k],a1=Ld[j0][k+1],a2=Ld[j0][k+2],a3=Ld[j0][k+3];
                float b1v=a1-a0*t10;
                float b2v=a2-a0*t20-b1v*t21;
                float b3v=a3-a0*t30-b1v*t31-b2v*t32;
                c00=a0*r0; c01=b1v*r1; c02=b2v*r2; c03=b3v*r3;
            }
            if (j1 < NB) {
                float a0=Ld[j1][k],a1=Ld[j1][k+1],a2=Ld[j1][k+2],a3=Ld[j1][k+3];
                float b1v=a1-a0*t10;
                float b2v=a2-a0*t20-b1v*t21;
                float b3v=a3-a0*t30-b1v*t31-b2v*t32;
                c10=a0*r0; c11=b1v*r1; c12=b2v*r2; c13=b3v*r3;
            }
            for (int i = k+1+ty; i < NB; i += 16) {
                float a0=Ld[i][k],a1=Ld[i][k+1],a2=Ld[i][k+2],a3=Ld[i][k+3];
                float b1v=a1-a0*t10;
                float b2v=a2-a0*t20-b1v*t21;
                float b3v=a3-a0*t30-b1v*t31-b2v*t32;
                if (tx == 0) {
                    colbuf[i][bb*3]   = b1v;
                    colbuf[i][bb*3+1] = b2v;
                    colbuf[i][bb*3+2] = b3v;
                }
                if (j0 <= i) Ld[i][j0] -= a0*c00 + b1v*c01 + b2v*c02 + b3v*c03;
                if (j1 <= i) Ld[i][j1] -= a0*c10 + b1v*c11 + b2v*c12 + b3v*c13;
            }
            __syncthreads();
        }
        // restore eliminated columns (final unscaled values incl. diagonals)
        for (int t2 = tid; t2 < NB*16; t2 += NT) {
            int i = t2 >> 4, bb = t2 & 15;
            int jb = bb*4, c = bb*3;
            float v1 = colbuf[i][c], v2 = colbuf[i][c+1], v3 = colbuf[i][c+2];
            if (i >= jb+1) Ld[i][jb+1] = v1;
            if (i >= jb+2) Ld[i][jb+2] = v2;
            if (i >= jb+3) Ld[i][jb+3] = v3;
        }
        __syncthreads();
        // scaling: pivots -> dinv/log; scale strictly-lower columns
        if (tid < NB) {
            float v = Ld[tid][tid];
            if (p == NPAN-1 && tid == NB-1) { s_quad = v; dinv[tid] = 1.f; }
            else { dinv[tid] = rsqrtf(v); logsum += logf(v); }   // log d_k
        }
        __syncthreads();
        for (int t2 = tid; t2 < NB*NB; t2 += NT) {
            int i = t2 >> 6, j = t2 & 63;
            if (i > j) Ld[i][j] *= dinv[j];
        }
        __syncthreads();

        // --- blocked right-looking TRSM: CTA `rank` owns row panel p+1+rank
        int r = p + 1 + rank;
        if (r < NPAN) {
            int r0 = r*NB;
            for (int t2 = tid; t2 < NB*16; t2 += NT) {
                int i = t2 >> 4, j4 = (t2 & 15) << 2;
                float4 v = __ldcg((const float4*)&g_S[(r0+i)*MP + c0 + j4]);
                Bs[i][j4]=v.x; Bs[i][j4+1]=v.y; Bs[i][j4+2]=v.z; Bs[i][j4+3]=v.w;
            }
            __syncthreads();
            int row = tid & 63, qq = tid >> 6;   // 8 col-streams
            #pragma unroll 1
            for (int blk = 0; blk < 8; blk++) {
                int cb = blk*8;
                if (tid < NB) {   // serial solve within 8-column block
                    #pragma unroll
                    for (int jj = 0; jj < 8; jj++) {
                        int j = cb + jj;
                        float a = Bs[tid][j];
                        for (int c = cb; c < j; c++) a -= Bs[tid][c]*Ld[j][c];
                        Bs[tid][j] = a * dinv[j];
                    }
                }
                __syncthreads();
                if (blk < 7) {    // parallel update of later columns
                    float rb[8];
                    #pragma unroll
                    for (int c = 0; c < 8; c++) rb[c] = Bs[row][cb+c];
                    for (int j = cb+8+qq; j < NB; j += 8) {
                        float s = 0.f;
                        #pragma unroll
                        for (int c = 0; c < 8; c++) s += rb[c]*Ld[j][cb+c];
                        Bs[row][j] -= s;
                    }
                    __syncthreads();
                }
            }
            for (int t2 = tid; t2 < NB*16; t2 += NT) {
                int i = t2 >> 4, j4 = (t2 & 15) << 2;
                float4 v = make_float4(Bs[i][j4],Bs[i][j4+1],Bs[i][j4+2],Bs[i][j4+3]);
                *(float4*)&g_S[(r0+i)*MP + c0 + j4] = v;
            }
        }

        if (p < NPAN-1) {
            CLUSTER_SYNC();
            // --- SYRK trailing update, tiles distributed over cluster ------
            int T = NPAN-1-p;
            int ntiles = T*(T+1)/2;
            for (int t0 = rank; t0 < ntiles; t0 += CL) {
                int idx = t0, bi = 0;
                while (idx >= bi+1){ idx -= bi+1; bi++; }
                int bj = idx;
                int rI = (p+1+bi)*NB, rJ = (p+1+bj)*NB;
                for (int t2 = tid; t2 < NB*16; t2 += NT) {
                    int i = t2 >> 4, j4 = (t2 & 15) << 2;
                    float4 v = __ldcg((const float4*)&g_S[(rI+i)*MP + c0 + j4]);
                    Ld[i][j4]=v.x; Ld[i][j4+1]=v.y; Ld[i][j4+2]=v.z; Ld[i][j4+3]=v.w;
                }
                if (bi != bj) {
                    for (int t2 = tid; t2 < NB*16; t2 += NT) {
                        int i = t2 >> 4, j4 = (t2 & 15) << 2;
                        float4 v = __ldcg((const float4*)&g_S[(rJ+i)*MP + c0 + j4]);
                        Bs[i][j4]=v.x; Bs[i][j4+1]=v.y; Bs[i][j4+2]=v.z; Bs[i][j4+3]=v.w;
                    }
                }
                __syncthreads();
                float (*Lj)[NB+1] = (bi==bj) ? Ld : Bs;
                // 512 threads: 2 rows x 4 cols each
                int sx = tid & 15, sy = tid >> 4;
                float acc[2][4] = {};
                #pragma unroll 4
                for (int kk = 0; kk < NB; kk++) {
                    float av[2], bv[4];
                    av[0]=Ld[sy*2][kk]; av[1]=Ld[sy*2+1][kk];
                    #pragma unroll
                    for (int v2=0;v2<4;v2++) bv[v2]=Lj[sx*4+v2][kk];
                    #pragma unroll
                    for (int u=0;u<2;u++)
                        #pragma unroll
                        for (int v2=0;v2<4;v2++) acc[u][v2] += av[u]*bv[v2];
                }
                #pragma unroll
                for (int u=0;u<2;u++) {
                    float* ptr = &g_S[(rI+sy*2+u)*MP + rJ + sx*4];
                    float4 old = __ldcg((const float4*)ptr);
                    old.x -= acc[u][0]; old.y -= acc[u][1];
                    old.z -= acc[u][2]; old.w -= acc[u][3];
                    *(float4*)ptr = old;
                }
                __syncthreads();
            }
            CLUSTER_SYNC();
        }
    }

    // ---------------- epilogue: loss (rank 0) ------------------------------
    if (rank == 0) {
        if (tid < NB) dinv[tid] = logsum;
        __syncthreads();
        if (tid == 0) {
            float l = 0.f;
            for (int k2 = 0; k2 < NB; k2++) l += dinv[k2];   // logdet S
            double quad1 = -(double)s_quad;
            double ed = (double)e;
            double rTrv = __ldcg(&g_rTr);
            double ldD0v = __ldcg(&g_ldD0);
            double q0v  = __ldcg(&g_q0);
            double logdetV = (double)(n - (NQ0 + NQ1)) * log(ed) + ldD0v + (double)l;
            double quad = (rTrv - q0v - quad1) / ed;
            double loss = 0.5 * (double)n * 1.8378770664093454836
                        + 0.5 * logdetV + 0.5 * quad;
            out[0] = (float)loss;
        }
    }
}

// ---------------- host launcher --------------------------------------------
extern "C" void kernel_launch(void* const* d_in, const int* in_sizes, int n_in,
                              void* d_out, int out_size) {
    const float* y_true = (const float*)d_in[0];
    const float* y_pred = (const float*)d_in[1];
    const void*  z0     = d_in[2];
    const void*  z1     = d_in[3];
    const float* sig2e  = (const float*)d_in[4];
    const float* sig2bs = (const float*)d_in[5];
    float* out = (float*)d_out;
    int n = in_sizes[0];

    k_all<<<CL, NT>>>(y_true, y_pred, z0, z1, sig2e, sig2bs, out, n);
}